// round 16
// baseline (speedup 1.0000x reference)
#include <cuda_runtime.h>
#include <cuda_fp16.h>
#include <cstdint>

#define B_ 2
#define S_ 2048
#define E_ 768
#define H_ 12
#define D_ 64
#define M_ (B_*S_)
#define PK 40   // proj smem stride (halfs)
#define PD 72   // attn smem stride (halfs)
#define LOG2E 1.44269504f

// fp16 Q/K/V outputs + fp16 copies of inputs/weights + P cache (device globals)
__device__ __half g_qhi[(size_t)B_*H_*S_*D_];
__device__ __half g_khi[(size_t)B_*H_*S_*D_];
__device__ __half g_vhi[(size_t)B_*H_*S_*D_];
__device__ __half g_xq[(size_t)M_*E_];
__device__ __half g_xk[(size_t)M_*E_];
__device__ __half g_xv[(size_t)M_*E_];
__device__ __half g_wq[(size_t)E_*E_];
__device__ __half g_wk[(size_t)E_*E_];
__device__ __half g_wv[(size_t)E_*E_];
__device__ __half g_pc[(size_t)B_*H_*S_*S_];   // masked exp(scores), fragment layout

// ---------------------------------------------------------------------------
// helpers
// ---------------------------------------------------------------------------
__device__ __forceinline__ uint32_t smem_u32(const void* p) {
    return (uint32_t)__cvta_generic_to_shared(p);
}
__device__ __forceinline__ void ldsm4(uint32_t r[4], uint32_t a) {
    asm volatile("ldmatrix.sync.aligned.m8n8.x4.shared.b16 {%0,%1,%2,%3}, [%4];"
                 : "=r"(r[0]), "=r"(r[1]), "=r"(r[2]), "=r"(r[3]) : "r"(a));
}
__device__ __forceinline__ void ldsm4t(uint32_t r[4], uint32_t a) {
    asm volatile("ldmatrix.sync.aligned.m8n8.x4.trans.shared.b16 {%0,%1,%2,%3}, [%4];"
                 : "=r"(r[0]), "=r"(r[1]), "=r"(r[2]), "=r"(r[3]) : "r"(a));
}
__device__ __forceinline__ void mma16816(float4& c, const uint32_t a[4], const uint32_t b[2]) {
    asm volatile(
        "mma.sync.aligned.m16n8k16.row.col.f32.f16.f16.f32 "
        "{%0,%1,%2,%3}, {%4,%5,%6,%7}, {%8,%9}, {%0,%1,%2,%3};"
        : "+f"(c.x), "+f"(c.y), "+f"(c.z), "+f"(c.w)
        : "r"(a[0]), "r"(a[1]), "r"(a[2]), "r"(a[3]), "r"(b[0]), "r"(b[1]));
}
__device__ __forceinline__ float ex2(float x) {
    float r;
    asm("ex2.approx.ftz.f32 %0, %1;" : "=f"(r) : "f"(x));
    return r;
}
__device__ __forceinline__ uint32_t cvt2(float x, float y) {
    __half2 h = __floats2half2_rn(x, y);
    return *(uint32_t*)&h;
}
__device__ __forceinline__ float2 h2f(uint32_t u) {
    return __half22float2(*(__half2*)&u);
}
__device__ __forceinline__ void cpa16(uint32_t dst, const void* src) {
    asm volatile("cp.async.ca.shared.global [%0], [%1], 16;" :: "r"(dst), "l"(src));
}
#define CP_COMMIT() asm volatile("cp.async.commit_group;")
#define CP_WAIT0()  asm volatile("cp.async.wait_group 0;")

// ---------------------------------------------------------------------------
// One-shot fp32 -> fp16 conversion of inputs and weights.
// ---------------------------------------------------------------------------
__global__ __launch_bounds__(256) void cvt6(const float* __restrict__ xq,
                                            const float* __restrict__ xk,
                                            const float* __restrict__ xv,
                                            const float* __restrict__ wq,
                                            const float* __restrict__ wk,
                                            const float* __restrict__ wv) {
    const int t = blockIdx.y;
    const float* src = (t == 0) ? xq : (t == 1) ? xk : (t == 2) ? xv
                     : (t == 3) ? wq : (t == 4) ? wk : wv;
    __half* dst = (t == 0) ? g_xq : (t == 1) ? g_xk : (t == 2) ? g_xv
                : (t == 3) ? g_wq : (t == 4) ? g_wk : g_wv;
    const int n4 = (t < 3) ? (M_ * E_ / 4) : (E_ * E_ / 4);
    int i = blockIdx.x * 256 + threadIdx.x;
    if (i >= n4) return;
    float4 v = ((const float4*)src)[i];
    ((uint2*)dst)[i] = make_uint2(cvt2(v.x, v.y), cvt2(v.z, v.w));
}

// ---------------------------------------------------------------------------
// Fused projection GEMM (pure fp16 pipeline, unchanged from R15 best).
// ---------------------------------------------------------------------------
__global__ __launch_bounds__(256, 2) void proj_mma(int dummy) {
    extern __shared__ __half psm[];
    __half* Xs = psm;               // [2][128][PK]
    __half* Ws = psm + 10240;       // [2][64][PK]
    #define XH(buf,row,k) ((buf)*5120 + (row)*PK + (k))
    #define WH(buf,row,k) ((buf)*2560 + (row)*PK + (k))

    const int z = blockIdx.z;
    const __half* Xg = (z == 0) ? g_xq : (z == 1) ? g_xk : g_xv;
    const __half* Wg = (z == 0) ? g_wq : (z == 1) ? g_wk : g_wv;
    __half* ohi = (z == 0) ? g_qhi : (z == 1) ? g_khi : g_vhi;
    const float scale = (z == 0) ? 0.125f * LOG2E : 1.0f;

    const int tid  = threadIdx.x;
    const int lane = tid & 31;
    const int wid  = tid >> 5;
    const int wm = wid & 3;
    const int wn = wid >> 2;
    const int i0 = blockIdx.y * 128;
    const int o0 = blockIdx.x * 64;

    auto load_tiles = [&](int e0, int buf) {
        #pragma unroll
        for (int p = 0; p < 2; p++) {
            int idx = tid + p * 256;
            int row = idx >> 2, ch = idx & 3;
            cpa16(smem_u32(&Xs[XH(buf, row, ch * 8)]),
                  Xg + (size_t)(i0 + row) * E_ + e0 + ch * 8);
        }
        {
            int row = tid >> 2, ch = tid & 3;
            cpa16(smem_u32(&Ws[WH(buf, row, ch * 8)]),
                  Wg + (size_t)(o0 + row) * E_ + e0 + ch * 8);
        }
    };

    float4 c[2][4];
    #pragma unroll
    for (int m = 0; m < 2; m++)
        #pragma unroll
        for (int t = 0; t < 4; t++) c[m][t] = make_float4(0.f, 0.f, 0.f, 0.f);

    load_tiles(0, 0); CP_COMMIT();

    for (int it = 0; it < 24; it++) {
        CP_WAIT0();
        __syncthreads();
        if (it < 23) { load_tiles((it + 1) * 32, (it & 1) ^ 1); CP_COMMIT(); }
        const int buf = it & 1;
        #pragma unroll
        for (int kc = 0; kc < 2; kc++) {
            uint32_t ahi[2][4];
            #pragma unroll
            for (int mt = 0; mt < 2; mt++) {
                int arow = wm*32 + mt*16 + (lane & 15);
                int acol = kc*16 + ((lane >> 4) & 1)*8;
                ldsm4(ahi[mt], smem_u32(&Xs[XH(buf, arow, acol)]));
            }
            #pragma unroll
            for (int np = 0; np < 2; np++) {
                int brow = wn*32 + np*16 + ((lane >> 4) & 1)*8 + (lane & 7);
                int bcol = kc*16 + ((lane >> 3) & 1)*8;
                uint32_t bhi[4];
                ldsm4(bhi, smem_u32(&Ws[WH(buf, brow, bcol)]));
                #pragma unroll
                for (int t = 0; t < 2; t++) {
                    int nt = np*2 + t;
                    #pragma unroll
                    for (int mt = 0; mt < 2; mt++)
                        mma16816(c[mt][nt], ahi[mt], bhi + 2*t);
                }
            }
        }
        __syncthreads();
    }

    const int h = blockIdx.x;
    const int g = lane >> 2, cc2 = (lane & 3) * 2;
    #pragma unroll
    for (int mt = 0; mt < 2; mt++) {
        #pragma unroll
        for (int nt = 0; nt < 4; nt++) {
            int d = wn * 32 + nt * 8 + cc2;
            #pragma unroll
            for (int rr = 0; rr < 2; rr++) {
                int ii = i0 + wm * 32 + mt * 16 + g + rr * 8;
                int b0 = ii >> 11, ss = ii & (S_ - 1);
                size_t off = ((size_t)(b0 * H_ + h) * S_ + ss) * D_ + d;
                float p0 = (rr ? c[mt][nt].z : c[mt][nt].x) * scale;
                float p1 = (rr ? c[mt][nt].w : c[mt][nt].y) * scale;
                *(uint32_t*)&ohi[off] = cvt2(p0, p1);
            }
        }
    }
    #undef XH
    #undef WH
}

// ---------------------------------------------------------------------------
// Two-phase attention with gmem P-cache. Block = (b,h) x 64 q rows, 2 warps.
// Phase A: QK + mask + ex2 -> rowsums; stores masked exp(scores) as packed
//   fp16 fragments (thread-contiguous, 8xSTG.128/tile) to g_pc.
// Phase B: loads P fragments back (8xLDG.128/tile) — NO K tile, NO QK mma,
//   NO exp — writes normalized attn, runs AV mma with fp16 V.
// ---------------------------------------------------------------------------
__global__ void __launch_bounds__(64, 4) attn_mma2(const int* __restrict__ mask,
                                                   float* __restrict__ out,
                                                   float* __restrict__ attn) {
    extern __shared__ __half sm[];
    __half* KB0 = sm;                         // 64 x PD
    __half* KB1 = sm + 1 * 64 * PD;
    __half* VH0 = sm + 2 * 64 * PD;
    __half* VH1 = sm + 3 * 64 * PD;
    float*  msks = (float*)(sm + 4 * 64 * PD);   // [S_] multiplicative mask

    const int tid  = threadIdx.x;
    const int lane = tid & 31, wid = tid >> 5;   // wid 0..1
    const int g = lane >> 2, cc2 = (lane & 3) * 2;
    const int bh = blockIdx.y;
    const int b  = bh / H_;
    const int h  = bh - b * H_;
    const int s0 = blockIdx.x * 64;
    const int wq = wid * 32;

    const __half* qh = g_qhi + ((size_t)bh * S_ + s0) * D_;
    const __half* kh = g_khi + (size_t)bh * S_ * D_;
    const __half* vhp = g_vhi + (size_t)bh * S_ * D_;
    // P-cache base for this CTA: [bh][s0tile] block of 32 tiles x 64 thr x 64 halfs
    __half* pcb = g_pc + ((size_t)bh * (S_ / 64) + blockIdx.x) * (32 * 64 * 64)
                       + (size_t)tid * 64;

    // whole-row multiplicative mask -> smem (once)
    const int* mrow = mask + b * S_;
    for (int t = tid; t < S_; t += 64) msks[t] = mrow[t] ? 0.f : 1.f;

    // ---- stage Q, extract frags (2 m-tiles per warp) ----
    #pragma unroll
    for (int p = 0; p < 8; p++) {
        int c = tid + p * 64;
        int row = c >> 3, col = (c & 7) * 8;
        cpa16(smem_u32(KB0 + row * PD + col), qh + row * 64 + col);
    }
    CP_COMMIT(); CP_WAIT0();
    __syncthreads();
    uint32_t Qhi[2][4][4];
    #pragma unroll
    for (int mt = 0; mt < 2; mt++) {
        #pragma unroll
        for (int d = 0; d < 4; d++) {
            int r = wq + mt*16 + (lane & 15);
            int cofs = d*16 + ((lane >> 4) & 1)*8;
            ldsm4(Qhi[mt][d], smem_u32(KB0 + r * PD + cofs));
        }
    }
    __syncthreads();

    auto loadK = [&](int kb, __half* dst) {
        const __half* src = kh + (size_t)kb * 64 * 64;
        #pragma unroll
        for (int p = 0; p < 8; p++) {
            int c = tid + p * 64;
            int row = c >> 3, col = (c & 7) * 8;
            cpa16(smem_u32(dst + row * PD + col), src + row * 64 + col);
        }
    };
    auto loadV = [&](int kb, __half* dh) {
        const __half* sh = vhp + (size_t)kb * 64 * 64;
        #pragma unroll
        for (int p = 0; p < 8; p++) {
            int c = tid + p * 64;
            int row = c >> 3, col = (c & 7) * 8;
            cpa16(smem_u32(dh + row * PD + col), sh + row * 64 + col);
        }
    };

    const int krow_off = ((lane >> 4) & 1) * 8 + (lane & 7);
    const int kcol_off = ((lane >> 3) & 1) * 8;
    const int vrow_off = lane & 15;
    const int vcol_off = ((lane >> 4) & 1) * 8;

    // ================= Phase A: rowsums + P store =================
    float rs[2][2] = {{0.f, 0.f}, {0.f, 0.f}};
    loadK(0, KB0); CP_COMMIT();
    for (int kb = 0; kb < 32; kb++) {
        CP_WAIT0();
        __syncthreads();
        if (kb < 31) { loadK(kb + 1, (kb & 1) ? KB0 : KB1); CP_COMMIT(); }
        __half* KK = (kb & 1) ? KB1 : KB0;
        const float* mt_ = msks + kb * 64;
        uint32_t arr[32];
        #pragma unroll
        for (int nt2 = 0; nt2 < 4; nt2++) {
            float4 sA[2], sB[2];
            #pragma unroll
            for (int mt = 0; mt < 2; mt++) {
                sA[mt] = make_float4(0.f, 0.f, 0.f, 0.f);
                sB[mt] = make_float4(0.f, 0.f, 0.f, 0.f);
            }
            #pragma unroll
            for (int d = 0; d < 4; d++) {
                uint32_t kf[4];
                ldsm4(kf, smem_u32(KK + (nt2*16 + krow_off) * PD + d*16 + kcol_off));
                #pragma unroll
                for (int mt = 0; mt < 2; mt++) {
                    mma16816(sA[mt], Qhi[mt][d], kf);
                    mma16816(sB[mt], Qhi[mt][d], kf + 2);
                }
            }
            float ma = mt_[nt2*16 + cc2],     mb = mt_[nt2*16 + cc2 + 1];
            float mc = mt_[nt2*16 + 8 + cc2], md = mt_[nt2*16 + 8 + cc2 + 1];
            #pragma unroll
            for (int mt = 0; mt < 2; mt++) {
                float p0 = ma * ex2(sA[mt].x), p1 = mb * ex2(sA[mt].y);
                float p2 = ma * ex2(sA[mt].z), p3 = mb * ex2(sA[mt].w);
                float q0 = mc * ex2(sB[mt].x), q1 = md * ex2(sB[mt].y);
                float q2 = mc * ex2(sB[mt].z), q3 = md * ex2(sB[mt].w);
                rs[mt][0] += p0 + p1 + q0 + q1;
                rs[mt][1] += p2 + p3 + q2 + q3;
                arr[mt*16 + nt2*4 + 0] = cvt2(p0, p1);
                arr[mt*16 + nt2*4 + 1] = cvt2(p2, p3);
                arr[mt*16 + nt2*4 + 2] = cvt2(q0, q1);
                arr[mt*16 + nt2*4 + 3] = cvt2(q2, q3);
            }
        }
        // store P fragments: thread-contiguous 128B, 8x STG.128
        uint4* pp = (uint4*)(pcb + (size_t)kb * 4096);
        #pragma unroll
        for (int r = 0; r < 8; r++)
            pp[r] = make_uint4(arr[4*r], arr[4*r+1], arr[4*r+2], arr[4*r+3]);
    }
    float inv0[2], inv1[2];
    #pragma unroll
    for (int mt = 0; mt < 2; mt++) {
        float a0 = rs[mt][0], a1 = rs[mt][1];
        a0 += __shfl_xor_sync(0xffffffffu, a0, 1);
        a0 += __shfl_xor_sync(0xffffffffu, a0, 2);
        a1 += __shfl_xor_sync(0xffffffffu, a1, 1);
        a1 += __shfl_xor_sync(0xffffffffu, a1, 2);
        inv0[mt] = 1.0f / a0;
        inv1[mt] = 1.0f / a1;
    }

    // ================= Phase B: attn write + AV (no K, no QK, no exp) ======
    float4 o[2][8];
    #pragma unroll
    for (int mt = 0; mt < 2; mt++)
        #pragma unroll
        for (int t = 0; t < 8; t++) o[mt][t] = make_float4(0.f, 0.f, 0.f, 0.f);

    loadV(0, VH0); CP_COMMIT();
    for (int kb = 0; kb < 32; kb++) {
        // load P fragments back (independent of V pipeline)
        uint32_t arr[32];
        const uint4* pp = (const uint4*)(pcb + (size_t)kb * 4096);
        #pragma unroll
        for (int r = 0; r < 8; r++) {
            uint4 v = pp[r];
            arr[4*r] = v.x; arr[4*r+1] = v.y; arr[4*r+2] = v.z; arr[4*r+3] = v.w;
        }
        CP_WAIT0();
        __syncthreads();
        if (kb < 31) { loadV(kb + 1, (kb & 1) ? VH0 : VH1); CP_COMMIT(); }
        __half* VVh = (kb & 1) ? VH1 : VH0;

        // normalized attn writes
        #pragma unroll
        for (int nt2 = 0; nt2 < 4; nt2++) {
            size_t col = (size_t)kb * 64 + nt2 * 16 + cc2;
            #pragma unroll
            for (int mt = 0; mt < 2; mt++) {
                float2 f01 = h2f(arr[mt*16 + nt2*4 + 0]);
                float2 f23 = h2f(arr[mt*16 + nt2*4 + 1]);
                float2 g01 = h2f(arr[mt*16 + nt2*4 + 2]);
                float2 g23 = h2f(arr[mt*16 + nt2*4 + 3]);
                int srow = s0 + wq + mt * 16 + g;
                float* r0p = &attn[((size_t)bh * S_ + srow) * S_ + col];
                float* r1p = &attn[((size_t)bh * S_ + srow + 8) * S_ + col];
                __stcs((float2*)r0p,       make_float2(f01.x * inv0[mt], f01.y * inv0[mt]));
                __stcs((float2*)(r0p + 8), make_float2(g01.x * inv0[mt], g01.y * inv0[mt]));
                __stcs((float2*)r1p,       make_float2(f23.x * inv1[mt], f23.y * inv1[mt]));
                __stcs((float2*)(r1p + 8), make_float2(g23.x * inv1[mt], g23.y * inv1[mt]));
            }
        }

        // AV
        #pragma unroll
        for (int dt2 = 0; dt2 < 4; dt2++) {
            #pragma unroll
            for (int j = 0; j < 4; j++) {
                uint32_t vh[4];
                ldsm4t(vh, smem_u32(VVh + (j*16 + vrow_off) * PD + dt2*16 + vcol_off));
                #pragma unroll
                for (int mt = 0; mt < 2; mt++) {
                    mma16816(o[mt][2*dt2],     &arr[mt*16 + j*4], vh);
                    mma16816(o[mt][2*dt2 + 1], &arr[mt*16 + j*4], vh + 2);
                }
            }
        }
    }

    // ---- finalize ----
    #pragma unroll
    for (int mt = 0; mt < 2; mt++) {
        int srow = s0 + wq + mt * 16 + g;
        #pragma unroll
        for (int dt = 0; dt < 8; dt++) {
            int d = dt * 8 + cc2;
            *(float2*)&out[(((size_t)b * S_ + srow) * H_ + h) * D_ + d] =
                make_float2(o[mt][dt].x * inv0[mt], o[mt][dt].y * inv0[mt]);
            *(float2*)&out[(((size_t)b * S_ + srow + 8) * H_ + h) * D_ + d] =
                make_float2(o[mt][dt].z * inv1[mt], o[mt][dt].w * inv1[mt]);
        }
    }
}

// ---------------------------------------------------------------------------
extern "C" void kernel_launch(void* const* d_in, const int* in_sizes, int n_in,
                              void* d_out, int out_size) {
    (void)in_sizes; (void)n_in; (void)out_size;
    const float* query = (const float*)d_in[0];
    const float* key   = (const float*)d_in[1];
    const float* value = (const float*)d_in[2];
    const int*   mask  = (const int*)d_in[3];
    const float* Wq    = (const float*)d_in[4];
    const float* Wk    = (const float*)d_in[5];
    const float* Wv    = (const float*)d_in[6];

    float* out  = (float*)d_out;                        // attn_output [B,S,E]
    float* attn = out + (size_t)B_ * S_ * E_;           // attn [B,H,S,S]

    dim3 cgrid(M_ * E_ / 4 / 256, 6);
    cvt6<<<cgrid, 256>>>(query, key, value, Wq, Wk, Wv);

    int proj_smem = 15360 * (int)sizeof(__half);        // 30720 B
    cudaFuncSetAttribute(proj_mma, cudaFuncAttributeMaxDynamicSharedMemorySize, proj_smem);
    dim3 pgrid(E_ / 64, M_ / 128, 3);
    proj_mma<<<pgrid, 256, proj_smem>>>(0);

    int smem_bytes = 4 * 64 * PD * (int)sizeof(__half) + S_ * (int)sizeof(float); // 45056
    cudaFuncSetAttribute(attn_mma2, cudaFuncAttributeMaxDynamicSharedMemorySize, smem_bytes);
    attn_mma2<<<dim3(S_ / 64, B_ * H_), 64, smem_bytes>>>(mask, out, attn);
}

// round 17
// speedup vs baseline: 1.1603x; 1.1603x over previous
#include <cuda_runtime.h>
#include <cuda_fp16.h>
#include <cstdint>

#define B_ 2
#define S_ 2048
#define E_ 768
#define H_ 12
#define D_ 64
#define M_ (B_*S_)
#define PK 40   // proj smem stride (halfs)
#define PD 72   // attn smem stride (halfs)
#define LOG2E 1.44269504f

// fp16 Q/K/V outputs + fp16 copies of inputs/weights (device globals)
__device__ __half g_qhi[(size_t)B_*H_*S_*D_];
__device__ __half g_khi[(size_t)B_*H_*S_*D_];
__device__ __half g_vhi[(size_t)B_*H_*S_*D_];
__device__ __half g_xq[(size_t)M_*E_];
__device__ __half g_xk[(size_t)M_*E_];
__device__ __half g_xv[(size_t)M_*E_];
__device__ __half g_wq[(size_t)E_*E_];
__device__ __half g_wk[(size_t)E_*E_];
__device__ __half g_wv[(size_t)E_*E_];

// ---------------------------------------------------------------------------
// helpers
// ---------------------------------------------------------------------------
__device__ __forceinline__ uint32_t smem_u32(const void* p) {
    return (uint32_t)__cvta_generic_to_shared(p);
}
__device__ __forceinline__ void ldsm4(uint32_t r[4], uint32_t a) {
    asm volatile("ldmatrix.sync.aligned.m8n8.x4.shared.b16 {%0,%1,%2,%3}, [%4];"
                 : "=r"(r[0]), "=r"(r[1]), "=r"(r[2]), "=r"(r[3]) : "r"(a));
}
__device__ __forceinline__ void ldsm4t(uint32_t r[4], uint32_t a) {
    asm volatile("ldmatrix.sync.aligned.m8n8.x4.trans.shared.b16 {%0,%1,%2,%3}, [%4];"
                 : "=r"(r[0]), "=r"(r[1]), "=r"(r[2]), "=r"(r[3]) : "r"(a));
}
__device__ __forceinline__ void mma16816(float4& c, const uint32_t a[4], const uint32_t b[2]) {
    asm volatile(
        "mma.sync.aligned.m16n8k16.row.col.f32.f16.f16.f32 "
        "{%0,%1,%2,%3}, {%4,%5,%6,%7}, {%8,%9}, {%0,%1,%2,%3};"
        : "+f"(c.x), "+f"(c.y), "+f"(c.z), "+f"(c.w)
        : "r"(a[0]), "r"(a[1]), "r"(a[2]), "r"(a[3]), "r"(b[0]), "r"(b[1]));
}
__device__ __forceinline__ float ex2(float x) {
    float r;
    asm("ex2.approx.ftz.f32 %0, %1;" : "=f"(r) : "f"(x));
    return r;
}
__device__ __forceinline__ uint32_t cvt2(float x, float y) {
    __half2 h = __floats2half2_rn(x, y);
    return *(uint32_t*)&h;
}
__device__ __forceinline__ void cpa16(uint32_t dst, const void* src) {
    asm volatile("cp.async.ca.shared.global [%0], [%1], 16;" :: "r"(dst), "l"(src));
}
#define CP_COMMIT() asm volatile("cp.async.commit_group;")
#define CP_WAIT0()  asm volatile("cp.async.wait_group 0;")

// ---------------------------------------------------------------------------
// One-shot fp32 -> fp16 conversion of inputs and weights.
// ---------------------------------------------------------------------------
__global__ __launch_bounds__(256) void cvt6(const float* __restrict__ xq,
                                            const float* __restrict__ xk,
                                            const float* __restrict__ xv,
                                            const float* __restrict__ wq,
                                            const float* __restrict__ wk,
                                            const float* __restrict__ wv) {
    const int t = blockIdx.y;
    const float* src = (t == 0) ? xq : (t == 1) ? xk : (t == 2) ? xv
                     : (t == 3) ? wq : (t == 4) ? wk : wv;
    __half* dst = (t == 0) ? g_xq : (t == 1) ? g_xk : (t == 2) ? g_xv
                : (t == 3) ? g_wq : (t == 4) ? g_wk : g_wv;
    const int n4 = (t < 3) ? (M_ * E_ / 4) : (E_ * E_ / 4);
    int i = blockIdx.x * 256 + threadIdx.x;
    if (i >= n4) return;
    float4 v = ((const float4*)src)[i];
    ((uint2*)dst)[i] = make_uint2(cvt2(v.x, v.y), cvt2(v.z, v.w));
}

// ---------------------------------------------------------------------------
// Fused projection GEMM (pure fp16 pipeline). BM=128 BN=64 BK=32, 256 thr.
// ---------------------------------------------------------------------------
__global__ __launch_bounds__(256, 2) void proj_mma(int dummy) {
    extern __shared__ __half psm[];
    __half* Xs = psm;               // [2][128][PK]
    __half* Ws = psm + 10240;       // [2][64][PK]
    #define XH(buf,row,k) ((buf)*5120 + (row)*PK + (k))
    #define WH(buf,row,k) ((buf)*2560 + (row)*PK + (k))

    const int z = blockIdx.z;
    const __half* Xg = (z == 0) ? g_xq : (z == 1) ? g_xk : g_xv;
    const __half* Wg = (z == 0) ? g_wq : (z == 1) ? g_wk : g_wv;
    __half* ohi = (z == 0) ? g_qhi : (z == 1) ? g_khi : g_vhi;
    const float scale = (z == 0) ? 0.125f * LOG2E : 1.0f;

    const int tid  = threadIdx.x;
    const int lane = tid & 31;
    const int wid  = tid >> 5;
    const int wm = wid & 3;
    const int wn = wid >> 2;
    const int i0 = blockIdx.y * 128;
    const int o0 = blockIdx.x * 64;

    auto load_tiles = [&](int e0, int buf) {
        #pragma unroll
        for (int p = 0; p < 2; p++) {
            int idx = tid + p * 256;
            int row = idx >> 2, ch = idx & 3;
            cpa16(smem_u32(&Xs[XH(buf, row, ch * 8)]),
                  Xg + (size_t)(i0 + row) * E_ + e0 + ch * 8);
        }
        {
            int row = tid >> 2, ch = tid & 3;
            cpa16(smem_u32(&Ws[WH(buf, row, ch * 8)]),
                  Wg + (size_t)(o0 + row) * E_ + e0 + ch * 8);
        }
    };

    float4 c[2][4];
    #pragma unroll
    for (int m = 0; m < 2; m++)
        #pragma unroll
        for (int t = 0; t < 4; t++) c[m][t] = make_float4(0.f, 0.f, 0.f, 0.f);

    load_tiles(0, 0); CP_COMMIT();

    for (int it = 0; it < 24; it++) {
        CP_WAIT0();
        __syncthreads();
        if (it < 23) { load_tiles((it + 1) * 32, (it & 1) ^ 1); CP_COMMIT(); }
        const int buf = it & 1;
        #pragma unroll
        for (int kc = 0; kc < 2; kc++) {
            uint32_t ahi[2][4];
            #pragma unroll
            for (int mt = 0; mt < 2; mt++) {
                int arow = wm*32 + mt*16 + (lane & 15);
                int acol = kc*16 + ((lane >> 4) & 1)*8;
                ldsm4(ahi[mt], smem_u32(&Xs[XH(buf, arow, acol)]));
            }
            #pragma unroll
            for (int np = 0; np < 2; np++) {
                int brow = wn*32 + np*16 + ((lane >> 4) & 1)*8 + (lane & 7);
                int bcol = kc*16 + ((lane >> 3) & 1)*8;
                uint32_t bhi[4];
                ldsm4(bhi, smem_u32(&Ws[WH(buf, brow, bcol)]));
                #pragma unroll
                for (int t = 0; t < 2; t++) {
                    int nt = np*2 + t;
                    #pragma unroll
                    for (int mt = 0; mt < 2; mt++)
                        mma16816(c[mt][nt], ahi[mt], bhi + 2*t);
                }
            }
        }
        __syncthreads();
    }

    const int h = blockIdx.x;
    const int g = lane >> 2, cc2 = (lane & 3) * 2;
    #pragma unroll
    for (int mt = 0; mt < 2; mt++) {
        #pragma unroll
        for (int nt = 0; nt < 4; nt++) {
            int d = wn * 32 + nt * 8 + cc2;
            #pragma unroll
            for (int rr = 0; rr < 2; rr++) {
                int ii = i0 + wm * 32 + mt * 16 + g + rr * 8;
                int b0 = ii >> 11, ss = ii & (S_ - 1);
                size_t off = ((size_t)(b0 * H_ + h) * S_ + ss) * D_ + d;
                float p0 = (rr ? c[mt][nt].z : c[mt][nt].x) * scale;
                float p1 = (rr ? c[mt][nt].w : c[mt][nt].y) * scale;
                *(uint32_t*)&ohi[off] = cvt2(p0, p1);
            }
        }
    }
    #undef XH
    #undef WH
}

// ---------------------------------------------------------------------------
// Two-phase attention (R14/R15 structure), now 5 CTAs/SM: post-R14 register
// demand (~175, no Qlo) fits the 204-reg cap without hot spills; smem
// 45KB x 5 = 225KB binds occupancy. Block = (b,h) x 64 q rows, 2 warps.
// Phase A: QK + ex2 -> rowsums. Phase B: QK again (identical scores),
// normalized attn write (streaming), AV with fp16 V, normalized out.
// cp.async double-buffered, one sync per tile, x4 ldmatrix throughout.
// ---------------------------------------------------------------------------
__global__ void __launch_bounds__(64, 5) attn_mma2(const int* __restrict__ mask,
                                                   float* __restrict__ out,
                                                   float* __restrict__ attn) {
    extern __shared__ __half sm[];
    __half* KB0 = sm;                         // 64 x PD
    __half* KB1 = sm + 1 * 64 * PD;
    __half* VH0 = sm + 2 * 64 * PD;
    __half* VH1 = sm + 3 * 64 * PD;
    float*  msks = (float*)(sm + 4 * 64 * PD);   // [S_] multiplicative mask

    const int tid  = threadIdx.x;
    const int lane = tid & 31, wid = tid >> 5;   // wid 0..1
    const int g = lane >> 2, cc2 = (lane & 3) * 2;
    const int bh = blockIdx.y;
    const int b  = bh / H_;
    const int h  = bh - b * H_;
    const int s0 = blockIdx.x * 64;
    const int wq = wid * 32;                     // warp q-row base within CTA

    const __half* qh = g_qhi + ((size_t)bh * S_ + s0) * D_;
    const __half* kh = g_khi + (size_t)bh * S_ * D_;
    const __half* vhp = g_vhi + (size_t)bh * S_ * D_;

    // whole-row multiplicative mask -> smem (once)
    const int* mrow = mask + b * S_;
    for (int t = tid; t < S_; t += 64) msks[t] = mrow[t] ? 0.f : 1.f;

    // ---- stage Q, extract frags (2 m-tiles per warp) ----
    #pragma unroll
    for (int p = 0; p < 8; p++) {
        int c = tid + p * 64;
        int row = c >> 3, col = (c & 7) * 8;
        cpa16(smem_u32(KB0 + row * PD + col), qh + row * 64 + col);
    }
    CP_COMMIT(); CP_WAIT0();
    __syncthreads();
    uint32_t Qhi[2][4][4];
    #pragma unroll
    for (int mt = 0; mt < 2; mt++) {
        #pragma unroll
        for (int d = 0; d < 4; d++) {
            int r = wq + mt*16 + (lane & 15);
            int cofs = d*16 + ((lane >> 4) & 1)*8;
            ldsm4(Qhi[mt][d], smem_u32(KB0 + r * PD + cofs));
        }
    }
    __syncthreads();

    auto loadK = [&](int kb, __half* dst) {
        const __half* src = kh + (size_t)kb * 64 * 64;
        #pragma unroll
        for (int p = 0; p < 8; p++) {
            int c = tid + p * 64;
            int row = c >> 3, col = (c & 7) * 8;
            cpa16(smem_u32(dst + row * PD + col), src + row * 64 + col);
        }
    };
    auto loadV = [&](int kb, __half* dh) {
        const __half* sh = vhp + (size_t)kb * 64 * 64;
        #pragma unroll
        for (int p = 0; p < 8; p++) {
            int c = tid + p * 64;
            int row = c >> 3, col = (c & 7) * 8;
            cpa16(smem_u32(dh + row * PD + col), sh + row * 64 + col);
        }
    };

    const int krow_off = ((lane >> 4) & 1) * 8 + (lane & 7);
    const int kcol_off = ((lane >> 3) & 1) * 8;
    const int vrow_off = lane & 15;
    const int vcol_off = ((lane >> 4) & 1) * 8;

    // ================= Phase A: rowsums =================
    float rs[2][2] = {{0.f, 0.f}, {0.f, 0.f}};   // [mt][row-half]
    loadK(0, KB0); CP_COMMIT();
    for (int kb = 0; kb < 32; kb++) {
        CP_WAIT0();
        __syncthreads();
        if (kb < 31) { loadK(kb + 1, (kb & 1) ? KB0 : KB1); CP_COMMIT(); }
        __half* KK = (kb & 1) ? KB1 : KB0;
        const float* mt_ = msks + kb * 64;
        #pragma unroll
        for (int nt2 = 0; nt2 < 4; nt2++) {
            float4 sA[2], sB[2];
            #pragma unroll
            for (int mt = 0; mt < 2; mt++) {
                sA[mt] = make_float4(0.f, 0.f, 0.f, 0.f);
                sB[mt] = make_float4(0.f, 0.f, 0.f, 0.f);
            }
            #pragma unroll
            for (int d = 0; d < 4; d++) {
                uint32_t kf[4];
                ldsm4(kf, smem_u32(KK + (nt2*16 + krow_off) * PD + d*16 + kcol_off));
                #pragma unroll
                for (int mt = 0; mt < 2; mt++) {
                    mma16816(sA[mt], Qhi[mt][d], kf);
                    mma16816(sB[mt], Qhi[mt][d], kf + 2);
                }
            }
            float ma = mt_[nt2*16 + cc2],     mb = mt_[nt2*16 + cc2 + 1];
            float mc = mt_[nt2*16 + 8 + cc2], md = mt_[nt2*16 + 8 + cc2 + 1];
            #pragma unroll
            for (int mt = 0; mt < 2; mt++) {
                rs[mt][0] += ma * ex2(sA[mt].x) + mb * ex2(sA[mt].y)
                           + mc * ex2(sB[mt].x) + md * ex2(sB[mt].y);
                rs[mt][1] += ma * ex2(sA[mt].z) + mb * ex2(sA[mt].w)
                           + mc * ex2(sB[mt].z) + md * ex2(sB[mt].w);
            }
        }
    }
    float inv0[2], inv1[2];
    #pragma unroll
    for (int mt = 0; mt < 2; mt++) {
        float a0 = rs[mt][0], a1 = rs[mt][1];
        a0 += __shfl_xor_sync(0xffffffffu, a0, 1);
        a0 += __shfl_xor_sync(0xffffffffu, a0, 2);
        a1 += __shfl_xor_sync(0xffffffffu, a1, 1);
        a1 += __shfl_xor_sync(0xffffffffu, a1, 2);
        inv0[mt] = 1.0f / a0;
        inv1[mt] = 1.0f / a1;
    }

    // ================= Phase B: normalized attn + AV =================
    float4 o[2][8];
    #pragma unroll
    for (int mt = 0; mt < 2; mt++)
        #pragma unroll
        for (int t = 0; t < 8; t++) o[mt][t] = make_float4(0.f, 0.f, 0.f, 0.f);

    loadK(0, KB0); loadV(0, VH0); CP_COMMIT();
    for (int kb = 0; kb < 32; kb++) {
        CP_WAIT0();
        __syncthreads();
        if (kb < 31) {
            loadK(kb + 1, (kb & 1) ? KB0 : KB1);
            loadV(kb + 1, (kb & 1) ? VH0 : VH1);
            CP_COMMIT();
        }
        __half* KK  = (kb & 1) ? KB1 : KB0;
        __half* VVh = (kb & 1) ? VH1 : VH0;
        const float* mt_ = msks + kb * 64;

        uint32_t phi[2][4][4];
        #pragma unroll
        for (int nt2 = 0; nt2 < 4; nt2++) {
            float4 sA[2], sB[2];
            #pragma unroll
            for (int mt = 0; mt < 2; mt++) {
                sA[mt] = make_float4(0.f, 0.f, 0.f, 0.f);
                sB[mt] = make_float4(0.f, 0.f, 0.f, 0.f);
            }
            #pragma unroll
            for (int d = 0; d < 4; d++) {
                uint32_t kf[4];
                ldsm4(kf, smem_u32(KK + (nt2*16 + krow_off) * PD + d*16 + kcol_off));
                #pragma unroll
                for (int mt = 0; mt < 2; mt++) {
                    mma16816(sA[mt], Qhi[mt][d], kf);
                    mma16816(sB[mt], Qhi[mt][d], kf + 2);
                }
            }
            float ma = mt_[nt2*16 + cc2],     mb = mt_[nt2*16 + cc2 + 1];
            float mc = mt_[nt2*16 + 8 + cc2], md = mt_[nt2*16 + 8 + cc2 + 1];
            size_t col = (size_t)kb * 64 + nt2 * 16 + cc2;
            #pragma unroll
            for (int mt = 0; mt < 2; mt++) {
                float p0 = ma * ex2(sA[mt].x), p1 = mb * ex2(sA[mt].y);
                float p2 = ma * ex2(sA[mt].z), p3 = mb * ex2(sA[mt].w);
                float q0 = mc * ex2(sB[mt].x), q1 = md * ex2(sB[mt].y);
                float q2 = mc * ex2(sB[mt].z), q3 = md * ex2(sB[mt].w);

                int srow = s0 + wq + mt * 16 + g;
                float* r0p = &attn[((size_t)bh * S_ + srow) * S_ + col];
                float* r1p = &attn[((size_t)bh * S_ + srow + 8) * S_ + col];
                __stcs((float2*)r0p,       make_float2(p0 * inv0[mt], p1 * inv0[mt]));
                __stcs((float2*)(r0p + 8), make_float2(q0 * inv0[mt], q1 * inv0[mt]));
                __stcs((float2*)r1p,       make_float2(p2 * inv1[mt], p3 * inv1[mt]));
                __stcs((float2*)(r1p + 8), make_float2(q2 * inv1[mt], q3 * inv1[mt]));

                phi[mt][nt2][0] = cvt2(p0, p1);
                phi[mt][nt2][1] = cvt2(p2, p3);
                phi[mt][nt2][2] = cvt2(q0, q1);
                phi[mt][nt2][3] = cvt2(q2, q3);
            }
        }

        #pragma unroll
        for (int dt2 = 0; dt2 < 4; dt2++) {
            #pragma unroll
            for (int j = 0; j < 4; j++) {
                uint32_t vh[4];
                ldsm4t(vh, smem_u32(VVh + (j*16 + vrow_off) * PD + dt2*16 + vcol_off));
                #pragma unroll
                for (int mt = 0; mt < 2; mt++) {
                    mma16816(o[mt][2*dt2],     phi[mt][j], vh);
                    mma16816(o[mt][2*dt2 + 1], phi[mt][j], vh + 2);
                }
            }
        }
    }

    // ---- finalize ----
    #pragma unroll
    for (int mt = 0; mt < 2; mt++) {
        int srow = s0 + wq + mt * 16 + g;
        #pragma unroll
        for (int dt = 0; dt < 8; dt++) {
            int d = dt * 8 + cc2;
            *(float2*)&out[(((size_t)b * S_ + srow) * H_ + h) * D_ + d] =
                make_float2(o[mt][dt].x * inv0[mt], o[mt][dt].y * inv0[mt]);
            *(float2*)&out[(((size_t)b * S_ + srow + 8) * H_ + h) * D_ + d] =
                make_float2(o[mt][dt].z * inv1[mt], o[mt][dt].w * inv1[mt]);
        }
    }
}

// ---------------------------------------------------------------------------
extern "C" void kernel_launch(void* const* d_in, const int* in_sizes, int n_in,
                              void* d_out, int out_size) {
    (void)in_sizes; (void)n_in; (void)out_size;
    const float* query = (const float*)d_in[0];
    const float* key   = (const float*)d_in[1];
    const float* value = (const float*)d_in[2];
    const int*   mask  = (const int*)d_in[3];
    const float* Wq    = (const float*)d_in[4];
    const float* Wk    = (const float*)d_in[5];
    const float* Wv    = (const float*)d_in[6];

    float* out  = (float*)d_out;                        // attn_output [B,S,E]
    float* attn = out + (size_t)B_ * S_ * E_;           // attn [B,H,S,S]

    dim3 cgrid(M_ * E_ / 4 / 256, 6);
    cvt6<<<cgrid, 256>>>(query, key, value, Wq, Wk, Wv);

    int proj_smem = 15360 * (int)sizeof(__half);        // 30720 B
    cudaFuncSetAttribute(proj_mma, cudaFuncAttributeMaxDynamicSharedMemorySize, proj_smem);
    dim3 pgrid(E_ / 64, M_ / 128, 3);
    proj_mma<<<pgrid, 256, proj_smem>>>(0);

    int smem_bytes = 4 * 64 * PD * (int)sizeof(__half) + S_ * (int)sizeof(float); // 45056
    cudaFuncSetAttribute(attn_mma2, cudaFuncAttributeMaxDynamicSharedMemorySize, smem_bytes);
    attn_mma2<<<dim3(S_ / 64, B_ * H_), 64, smem_bytes>>>(mask, out, attn);
}